// round 15
// baseline (speedup 1.0000x reference)
#include <cuda_runtime.h>
#include <cuda_fp16.h>
#include <cstdint>

#define NN 50000
#define EE 640000
#define GGR 256
#define HH 128

// ---------------- scratch (device globals; no allocs allowed) ----------------
__device__ __align__(16) float g_h[NN * HH];
__device__ __align__(16) __half g_hb[NN * HH];
__device__ __align__(16) float g_z[NN * HH];
__device__ __align__(16) float g_tb[NN * HH];
__device__ __align__(16) __half g_e[(size_t)EE * HH];   // CSR-ordered edge features
__device__ int g_deg[NN];
__device__ int g_off[NN];
__device__ int g_cur[NN];
__device__ int g_bsum[64];
__device__ int g_eperm[EE];   // CSR slot -> edge id
__device__ int g_sperm[EE];   // CSR slot -> src node
__device__ float g_gate[NN];
__device__ float g_wexp[NN];
__device__ unsigned g_gmaxk[GGR];
__device__ float g_den[GGR];
__device__ __align__(16) float g_pool[GGR * HH];
__device__ __align__(16) float g_ht[GGR * HH];

// split-fp16 weights (hi/lo), [K][N] row-major with padded pitch
__device__ __align__(16) __half g_wnh[64 * 136],  g_wnl[64 * 136];
__device__ __align__(16) __half g_c1h[4 * 128 * 136], g_c1l[4 * 128 * 136];
__device__ __align__(16) __half g_c2h[4 * 128 * 136], g_c2l[4 * 128 * 136];
__device__ __align__(16) __half g_wgh[128 * 72],  g_wgl[128 * 72];
__device__ __align__(16) __half g_whh[128 * 136], g_whl[128 * 136];
__device__ __align__(16) __half g_e1h[16 * 136],  g_e1l[16 * 136];
__device__ __align__(16) __half g_e2h[128 * 136], g_e2l[128 * 136];

// ---------------- helpers ----------------
__device__ __forceinline__ uint32_t smem_u32(const void* p) {
    uint32_t a;
    asm("{ .reg .u64 t; cvta.to.shared.u64 t, %1; cvt.u32.u64 %0, t; }" : "=r"(a) : "l"(p));
    return a;
}
__device__ __forceinline__ uint32_t h2pack(float a, float b) {
    __half2 v = __floats2half2_rn(a, b);
    return *reinterpret_cast<uint32_t*>(&v);
}
__device__ __forceinline__ void wsplit(float x, __half& h, __half& l) {
    h = __float2half_rn(x);
    l = __float2half_rn(x - __half2float(h));
}
__device__ __forceinline__ void split2pack(float a, float b, uint32_t& hi, uint32_t& lo) {
    __half ha, la, hb_, lb;
    wsplit(a, ha, la);
    wsplit(b, hb_, lb);
    __half2 vh = __halves2half2(ha, hb_);
    __half2 vl = __halves2half2(la, lb);
    hi = *reinterpret_cast<uint32_t*>(&vh);
    lo = *reinterpret_cast<uint32_t*>(&vl);
}

__device__ __forceinline__ void ldsm_x4(uint32_t* r, uint32_t addr) {
    asm volatile("ldmatrix.sync.aligned.m8n8.x4.shared.b16 {%0,%1,%2,%3}, [%4];"
                 : "=r"(r[0]), "=r"(r[1]), "=r"(r[2]), "=r"(r[3]) : "r"(addr));
}
__device__ __forceinline__ void ldsm_x4t(uint32_t* r, uint32_t addr) {
    asm volatile("ldmatrix.sync.aligned.m8n8.x4.trans.shared.b16 {%0,%1,%2,%3}, [%4];"
                 : "=r"(r[0]), "=r"(r[1]), "=r"(r[2]), "=r"(r[3]) : "r"(addr));
}
__device__ __forceinline__ void mma16816(float* d, const uint32_t* a, const uint32_t* b) {
    asm volatile(
        "mma.sync.aligned.m16n8k16.row.col.f32.f16.f16.f32 "
        "{%0,%1,%2,%3}, {%4,%5,%6,%7}, {%8,%9}, {%0,%1,%2,%3};"
        : "+f"(d[0]), "+f"(d[1]), "+f"(d[2]), "+f"(d[3])
        : "r"(a[0]), "r"(a[1]), "r"(a[2]), "r"(a[3]), "r"(b[0]), "r"(b[1]));
}

// ---------------- fused weight prep: all 13 segments in one launch ----------------
struct PrepArg {
    const float* src;
    __half* hi;
    __half* lo;
    int N, PB, start, count;
};
struct PrepArgs {
    PrepArg a[13];
    int total;
};

__global__ void wprep_kernel(PrepArgs p) {
    int i = blockIdx.x * blockDim.x + threadIdx.x;
    if (i >= p.total) return;
#pragma unroll
    for (int s = 0; s < 13; s++) {
        if (i < p.a[s].start + p.a[s].count) {
            int local = i - p.a[s].start;
            int k = local / p.a[s].PB, n = local - k * p.a[s].PB;
            float x = (n < p.a[s].N) ? p.a[s].src[(size_t)k * p.a[s].N + n] : 0.f;
            __half h, l;
            wsplit(x, h, l);
            p.a[s].hi[local] = h;
            p.a[s].lo[local] = l;
            return;
        }
    }
}

// -------- 3-term tensor-core GEMM: C = op((Ah+Al) @ (Wh+Wl) + b), drop Al*Wl -------
template <int K, int NC, bool RELU, bool F16OUT>
__global__ void __launch_bounds__(256) mma_gemm(
    const float* __restrict__ A, const __half* __restrict__ Bhi,
    const __half* __restrict__ Blo, const float* __restrict__ bias,
    float* __restrict__ C, __half* __restrict__ Cb, int M) {
    constexpr int PA = K + 8;
    constexpr int PB = NC + 8;
    constexpr int NF = NC / 16;
    extern __shared__ __align__(16) char smc[];
    __half* Ah = (__half*)smc;
    __half* Al = Ah + 128 * PA;
    __half* Bh = Al + 128 * PA;
    __half* Bl = Bh + K * PB;

    const int tid = threadIdx.x;
    const int lane = tid & 31, w = tid >> 5;
    const int wm = (w & 3) * 32;
    const int wn = (w >> 2) * (NC / 2);
    const int m0 = blockIdx.x * 128;

    {
        const float4* sh = (const float4*)Bhi;
        const float4* sl = (const float4*)Blo;
        float4* dh = (float4*)Bh;
        float4* dl = (float4*)Bl;
        for (int i = tid; i < K * PB / 8; i += 256) { dh[i] = sh[i]; dl[i] = sl[i]; }
    }
    {
        int r = tid >> 1, half_ = tid & 1;
        int gr = m0 + r;
        bool v = gr < M;
        const float4* a4 = (const float4*)(A + (size_t)gr * K) + half_ * (K / 8);
        __half* th = Ah + r * PA + half_ * (K / 2);
        __half* tl = Al + r * PA + half_ * (K / 2);
#pragma unroll
        for (int i = 0; i < K / 8; i++) {
            float4 x = v ? a4[i] : make_float4(0.f, 0.f, 0.f, 0.f);
            uint32_t h0, l0, h1, l1;
            split2pack(x.x, x.y, h0, l0);
            split2pack(x.z, x.w, h1, l1);
            *(uint32_t*)(th + i * 4) = h0;
            *(uint32_t*)(th + i * 4 + 2) = h1;
            *(uint32_t*)(tl + i * 4) = l0;
            *(uint32_t*)(tl + i * 4 + 2) = l1;
        }
    }
    __syncthreads();

    float acc[2][NF][4];
#pragma unroll
    for (int i = 0; i < 2; i++)
#pragma unroll
        for (int j = 0; j < NF; j++)
#pragma unroll
            for (int q = 0; q < 4; q++) acc[i][j][q] = 0.f;

    const uint32_t Ahb = smem_u32(Ah), Alb = smem_u32(Al);
    const uint32_t Bhb = smem_u32(Bh), Blb = smem_u32(Bl);
    const int a_row = lane & 15, a_kof = (lane >> 4) << 3;
    const int b_mat = lane >> 3, b_r = lane & 7;
    const int b_krow = ((b_mat & 1) << 3) + b_r;
    const int b_ncol = (b_mat >> 1) << 3;

#pragma unroll
    for (int ks = 0; ks < K / 16; ks++) {
        const int k0 = ks * 16;
        uint32_t ahf[2][4], alf[2][4];
#pragma unroll
        for (int mi = 0; mi < 2; mi++) {
            uint32_t off = ((wm + mi * 16 + a_row) * PA + k0 + a_kof) * 2;
            ldsm_x4(ahf[mi], Ahb + off);
            ldsm_x4(alf[mi], Alb + off);
        }
#pragma unroll
        for (int np = 0; np < NF / 2; np++) {
            uint32_t off = ((k0 + b_krow) * PB + wn + np * 16 + b_ncol) * 2;
            uint32_t bhf[4], blf[4];
            ldsm_x4t(bhf, Bhb + off);
            ldsm_x4t(blf, Blb + off);
#pragma unroll
            for (int mi = 0; mi < 2; mi++) {
                mma16816(acc[mi][2 * np], ahf[mi], bhf);
                mma16816(acc[mi][2 * np], ahf[mi], blf);
                mma16816(acc[mi][2 * np], alf[mi], bhf);
                mma16816(acc[mi][2 * np + 1], ahf[mi], bhf + 2);
                mma16816(acc[mi][2 * np + 1], ahf[mi], blf + 2);
                mma16816(acc[mi][2 * np + 1], alf[mi], bhf + 2);
            }
        }
    }

    const int rbase = m0 + wm + (lane >> 2);
    const int cbase = wn + (lane & 3) * 2;
#pragma unroll
    for (int mi = 0; mi < 2; mi++) {
#pragma unroll
        for (int nj = 0; nj < NF; nj++) {
            int col = cbase + nj * 8;
            float b0 = bias[col], b1v = bias[col + 1];
#pragma unroll
            for (int hh = 0; hh < 2; hh++) {
                int row = rbase + mi * 16 + hh * 8;
                if (row < M) {
                    float v0 = acc[mi][nj][hh * 2 + 0] + b0;
                    float v1 = acc[mi][nj][hh * 2 + 1] + b1v;
                    if (RELU) { v0 = fmaxf(v0, 0.f); v1 = fmaxf(v1, 0.f); }
                    *(float2*)(C + (size_t)row * NC + col) = make_float2(v0, v1);
                    if (F16OUT)
                        *(uint32_t*)(Cb + (size_t)row * NC + col) = h2pack(v0, v1);
                }
            }
        }
    }
}

// ---------------- fused conv layer: h' = relu(BN(relu(z@W1)@W2)) -------------------
__global__ void __launch_bounds__(256) conv_fused_kernel(
    const float* __restrict__ Z,
    const __half* __restrict__ W1h, const __half* __restrict__ W1l,
    const __half* __restrict__ W2h, const __half* __restrict__ W2l,
    const float* __restrict__ b1, const float* __restrict__ b2,
    const float* __restrict__ gamma, const float* __restrict__ beta,
    float* __restrict__ Hout, __half* __restrict__ HBout, int M) {
    constexpr int PW = 136;
    extern __shared__ __align__(16) char smc[];
    __half* As = (__half*)smc;
    __half* Al = As + 128 * PW;
    __half* Q1h = Al + 128 * PW;
    __half* Q1l = Q1h + 128 * PW;
    __half* Q2h = Q1l + 128 * PW;
    __half* Q2l = Q2h + 128 * PW;

    const int tid = threadIdx.x;
    const int lane = tid & 31, w = tid >> 5;
    const int wm = (w & 3) * 32;
    const int wn = (w >> 2) * 64;
    const int m0 = blockIdx.x * 128;

    {
        const float4* s1h = (const float4*)W1h; const float4* s1l = (const float4*)W1l;
        const float4* s2h = (const float4*)W2h; const float4* s2l = (const float4*)W2l;
        float4* d1h = (float4*)Q1h; float4* d1l = (float4*)Q1l;
        float4* d2h = (float4*)Q2h; float4* d2l = (float4*)Q2l;
        for (int i = tid; i < 128 * PW / 8; i += 256) {
            d1h[i] = s1h[i]; d1l[i] = s1l[i];
            d2h[i] = s2h[i]; d2l[i] = s2l[i];
        }
    }
    {
        int r = tid >> 1, half_ = tid & 1;
        int gr = m0 + r;
        bool v = gr < M;
        const float4* a4 = (const float4*)(Z + (size_t)gr * 128) + half_ * 16;
        __half* th = As + r * PW + half_ * 64;
        __half* tl = Al + r * PW + half_ * 64;
#pragma unroll
        for (int i = 0; i < 16; i++) {
            float4 x = v ? a4[i] : make_float4(0.f, 0.f, 0.f, 0.f);
            uint32_t h0, l0, h1, l1;
            split2pack(x.x, x.y, h0, l0);
            split2pack(x.z, x.w, h1, l1);
            *(uint32_t*)(th + i * 4) = h0;
            *(uint32_t*)(th + i * 4 + 2) = h1;
            *(uint32_t*)(tl + i * 4) = l0;
            *(uint32_t*)(tl + i * 4 + 2) = l1;
        }
    }
    __syncthreads();

    const uint32_t Asb = smem_u32(As), Alb = smem_u32(Al);
    const uint32_t Q1hb = smem_u32(Q1h), Q1lb = smem_u32(Q1l);
    const uint32_t Q2hb = smem_u32(Q2h), Q2lb = smem_u32(Q2l);
    const int a_row = lane & 15, a_kof = (lane >> 4) << 3;
    const int b_mat = lane >> 3, b_r = lane & 7;
    const int b_krow = ((b_mat & 1) << 3) + b_r;
    const int b_ncol = (b_mat >> 1) << 3;
    const int frow = lane >> 2, fcol = (lane & 3) * 2;

    float acc[2][8][4];
#pragma unroll
    for (int i = 0; i < 2; i++)
#pragma unroll
        for (int j = 0; j < 8; j++)
#pragma unroll
            for (int q = 0; q < 4; q++) acc[i][j][q] = 0.f;

    // ---- phase 1: hidden = z @ W1 (3-term) ----
#pragma unroll
    for (int ks = 0; ks < 8; ks++) {
        const int k0 = ks * 16;
        uint32_t ahf[2][4], alf[2][4];
#pragma unroll
        for (int mi = 0; mi < 2; mi++) {
            uint32_t o = ((wm + mi * 16 + a_row) * PW + k0 + a_kof) * 2;
            ldsm_x4(ahf[mi], Asb + o);
            ldsm_x4(alf[mi], Alb + o);
        }
#pragma unroll
        for (int np = 0; np < 4; np++) {
            uint32_t o = ((k0 + b_krow) * PW + wn + np * 16 + b_ncol) * 2;
            uint32_t bhf[4], blf[4];
            ldsm_x4t(bhf, Q1hb + o);
            ldsm_x4t(blf, Q1lb + o);
#pragma unroll
            for (int mi = 0; mi < 2; mi++) {
                mma16816(acc[mi][2 * np], ahf[mi], bhf);
                mma16816(acc[mi][2 * np], ahf[mi], blf);
                mma16816(acc[mi][2 * np], alf[mi], bhf);
                mma16816(acc[mi][2 * np + 1], ahf[mi], bhf + 2);
                mma16816(acc[mi][2 * np + 1], ahf[mi], blf + 2);
                mma16816(acc[mi][2 * np + 1], alf[mi], bhf + 2);
            }
        }
    }
    __syncthreads();

    // relu(acc+b1) -> split back into As/Al
#pragma unroll
    for (int mi = 0; mi < 2; mi++) {
#pragma unroll
        for (int nj = 0; nj < 8; nj++) {
            int col = wn + nj * 8 + fcol;
            float c0 = b1[col], c1 = b1[col + 1];
#pragma unroll
            for (int hh = 0; hh < 2; hh++) {
                int row = wm + mi * 16 + hh * 8 + frow;
                float v0 = fmaxf(acc[mi][nj][hh * 2 + 0] + c0, 0.f);
                float v1 = fmaxf(acc[mi][nj][hh * 2 + 1] + c1, 0.f);
                uint32_t ph, pl;
                split2pack(v0, v1, ph, pl);
                *(uint32_t*)(As + row * PW + col) = ph;
                *(uint32_t*)(Al + row * PW + col) = pl;
            }
        }
    }
    __syncthreads();

    // ---- phase 2: out = hidden @ W2 (3-term) ----
#pragma unroll
    for (int i = 0; i < 2; i++)
#pragma unroll
        for (int j = 0; j < 8; j++)
#pragma unroll
            for (int q = 0; q < 4; q++) acc[i][j][q] = 0.f;
#pragma unroll
    for (int ks = 0; ks < 8; ks++) {
        const int k0 = ks * 16;
        uint32_t ahf[2][4], alf[2][4];
#pragma unroll
        for (int mi = 0; mi < 2; mi++) {
            uint32_t o = ((wm + mi * 16 + a_row) * PW + k0 + a_kof) * 2;
            ldsm_x4(ahf[mi], Asb + o);
            ldsm_x4(alf[mi], Alb + o);
        }
#pragma unroll
        for (int np = 0; np < 4; np++) {
            uint32_t o = ((k0 + b_krow) * PW + wn + np * 16 + b_ncol) * 2;
            uint32_t bhf[4], blf[4];
            ldsm_x4t(bhf, Q2hb + o);
            ldsm_x4t(blf, Q2lb + o);
#pragma unroll
            for (int mi = 0; mi < 2; mi++) {
                mma16816(acc[mi][2 * np], ahf[mi], bhf);
                mma16816(acc[mi][2 * np], ahf[mi], blf);
                mma16816(acc[mi][2 * np], alf[mi], bhf);
                mma16816(acc[mi][2 * np + 1], ahf[mi], bhf + 2);
                mma16816(acc[mi][2 * np + 1], ahf[mi], blf + 2);
                mma16816(acc[mi][2 * np + 1], alf[mi], bhf + 2);
            }
        }
    }

    const float bnsc = 0.99999500003749968f;
#pragma unroll
    for (int mi = 0; mi < 2; mi++) {
#pragma unroll
        for (int nj = 0; nj < 8; nj++) {
            int col = wn + nj * 8 + fcol;
            float c0 = b2[col], c1 = b2[col + 1];
            float g0 = bnsc * gamma[col], g1 = bnsc * gamma[col + 1];
            float t0 = beta[col], t1 = beta[col + 1];
#pragma unroll
            for (int hh = 0; hh < 2; hh++) {
                int row = m0 + wm + mi * 16 + hh * 8 + frow;
                if (row < M) {
                    float v0 = fmaxf((acc[mi][nj][hh * 2 + 0] + c0) * g0 + t0, 0.f);
                    float v1 = fmaxf((acc[mi][nj][hh * 2 + 1] + c1) * g1 + t1, 0.f);
                    *(float2*)(Hout + (size_t)row * 128 + col) = make_float2(v0, v1);
                    *(uint32_t*)(HBout + (size_t)row * 128 + col) = h2pack(v0, v1);
                }
            }
        }
    }
}

// -- fused edge encoder over CSR slots: e[slot] = fp16(relu(ea[eperm[slot]]@W1+b1)@W2+b2)
__global__ void __launch_bounds__(256) edge_mma_kernel(
    const float* __restrict__ EA,
    const __half* __restrict__ W1h, const __half* __restrict__ W1l,
    const __half* __restrict__ W2h, const __half* __restrict__ W2l,
    const float* __restrict__ b1, const float* __restrict__ b2,
    const int* __restrict__ eperm,
    __half* __restrict__ Eout, int E) {
    constexpr int PA1 = 24;
    constexpr int PW = 136;
    extern __shared__ __align__(16) char smc[];
    __half* A1 = (__half*)smc;         // 128*24
    __half* Q1h = A1 + 128 * PA1;      // 16*136
    __half* Q1l = Q1h + 16 * PW;
    __half* A2 = Q1l + 16 * PW;        // 128*136 (hidden, single fp16)
    __half* Q2h = A2 + 128 * PW;       // 128*136
    __half* Q2l = Q2h + 128 * PW;

    const int tid = threadIdx.x;
    const int lane = tid & 31, w = tid >> 5;
    const int wm = (w & 3) * 32;
    const int wn = (w >> 2) * 64;
    const int m0 = blockIdx.x * 128;

    {
        const float4* s1h = (const float4*)W1h; const float4* s1l = (const float4*)W1l;
        const float4* s2h = (const float4*)W2h; const float4* s2l = (const float4*)W2l;
        float4* d1h = (float4*)Q1h; float4* d1l = (float4*)Q1l;
        float4* d2h = (float4*)Q2h; float4* d2l = (float4*)Q2l;
        for (int i = tid; i < 16 * PW / 8; i += 256) { d1h[i] = s1h[i]; d1l[i] = s1l[i]; }
        for (int i = tid; i < 128 * PW / 8; i += 256) { d2h[i] = s2h[i]; d2l[i] = s2l[i]; }
    }
    // A1 fill: gather edge_attr rows through eperm (CSR slot -> edge id)
    {
        int r = tid >> 1, half_ = tid & 1;
        int slot = m0 + r;
        bool v = slot < E;
        int eid = v ? eperm[slot] : 0;
        const float4* a4 = (const float4*)(EA + (size_t)eid * 16) + half_ * 2;
        __half* ts = A1 + r * PA1 + half_ * 8;
#pragma unroll
        for (int i = 0; i < 2; i++) {
            float4 x = v ? a4[i] : make_float4(0.f, 0.f, 0.f, 0.f);
            *(uint32_t*)(ts + i * 4) = h2pack(x.x, x.y);
            *(uint32_t*)(ts + i * 4 + 2) = h2pack(x.z, x.w);
        }
    }
    __syncthreads();

    const int a_row = lane & 15, a_kof = (lane >> 4) << 3;
    const int b_mat = lane >> 3, b_r = lane & 7;
    const int b_krow = ((b_mat & 1) << 3) + b_r;
    const int b_ncol = (b_mat >> 1) << 3;
    const int frow = lane >> 2, fcol = (lane & 3) * 2;
    const uint32_t A1b = smem_u32(A1), Q1hb = smem_u32(Q1h), Q1lb = smem_u32(Q1l);
    const uint32_t A2b = smem_u32(A2), Q2hb = smem_u32(Q2h), Q2lb = smem_u32(Q2l);

    float acc[2][8][4];
#pragma unroll
    for (int i = 0; i < 2; i++)
#pragma unroll
        for (int j = 0; j < 8; j++)
#pragma unroll
            for (int q = 0; q < 4; q++) acc[i][j][q] = 0.f;

    // phase 1: single k16 step (A single, W split)
    {
        uint32_t af[2][4];
#pragma unroll
        for (int mi = 0; mi < 2; mi++)
            ldsm_x4(af[mi], A1b + ((wm + mi * 16 + a_row) * PA1 + a_kof) * 2);
#pragma unroll
        for (int np = 0; np < 4; np++) {
            uint32_t o = (b_krow * PW + wn + np * 16 + b_ncol) * 2;
            uint32_t bhf[4], blf[4];
            ldsm_x4t(bhf, Q1hb + o);
            ldsm_x4t(blf, Q1lb + o);
#pragma unroll
            for (int mi = 0; mi < 2; mi++) {
                mma16816(acc[mi][2 * np], af[mi], bhf);
                mma16816(acc[mi][2 * np], af[mi], blf);
                mma16816(acc[mi][2 * np + 1], af[mi], bhf + 2);
                mma16816(acc[mi][2 * np + 1], af[mi], blf + 2);
            }
        }
    }
#pragma unroll
    for (int mi = 0; mi < 2; mi++) {
#pragma unroll
        for (int nj = 0; nj < 8; nj++) {
            int col = wn + nj * 8 + fcol;
            float c0 = b1[col], c1 = b1[col + 1];
#pragma unroll
            for (int hh = 0; hh < 2; hh++) {
                int row = wm + mi * 16 + hh * 8 + frow;
                float v0 = fmaxf(acc[mi][nj][hh * 2 + 0] + c0, 0.f);
                float v1 = fmaxf(acc[mi][nj][hh * 2 + 1] + c1, 0.f);
                *(uint32_t*)(A2 + row * PW + col) = h2pack(v0, v1);
            }
        }
    }
    __syncthreads();

    // phase 2: e = hidden @ W2, K=128 (A single, W split)
#pragma unroll
    for (int i = 0; i < 2; i++)
#pragma unroll
        for (int j = 0; j < 8; j++)
#pragma unroll
            for (int q = 0; q < 4; q++) acc[i][j][q] = 0.f;
#pragma unroll
    for (int ks = 0; ks < 8; ks++) {
        const int k0 = ks * 16;
        uint32_t af[2][4];
#pragma unroll
        for (int mi = 0; mi < 2; mi++)
            ldsm_x4(af[mi], A2b + ((wm + mi * 16 + a_row) * PW + k0 + a_kof) * 2);
#pragma unroll
        for (int np = 0; np < 4; np++) {
            uint32_t o = ((k0 + b_krow) * PW + wn + np * 16 + b_ncol) * 2;
            uint32_t bhf[4], blf[4];
            ldsm_x4t(bhf, Q2hb + o);
            ldsm_x4t(blf, Q2lb + o);
#pragma unroll
            for (int mi = 0; mi < 2; mi++) {
                mma16816(acc[mi][2 * np], af[mi], bhf);
                mma16816(acc[mi][2 * np], af[mi], blf);
                mma16816(acc[mi][2 * np + 1], af[mi], bhf + 2);
                mma16816(acc[mi][2 * np + 1], af[mi], blf + 2);
            }
        }
    }
    // epilogue: sequential rows (CSR order)
#pragma unroll
    for (int mi = 0; mi < 2; mi++) {
#pragma unroll
        for (int nj = 0; nj < 8; nj++) {
            int col = wn + nj * 8 + fcol;
            float c0 = b2[col], c1 = b2[col + 1];
#pragma unroll
            for (int hh = 0; hh < 2; hh++) {
                int row = m0 + wm + mi * 16 + hh * 8 + frow;
                if (row < E) {
                    *(uint32_t*)(Eout + (size_t)row * 128 + col) =
                        h2pack(acc[mi][nj][hh * 2 + 0] + c0,
                               acc[mi][nj][hh * 2 + 1] + c1);
                }
            }
        }
    }
}

// ---------------- CSR build ----------------
__global__ void hist_kernel(const int* __restrict__ ei, int* __restrict__ deg, int E) {
    int e = blockIdx.x * blockDim.x + threadIdx.x;
    if (e < E) atomicAdd(&deg[ei[E + e]], 1);
}

__global__ __launch_bounds__(1024) void scan1_kernel(const int* __restrict__ deg,
                                                     int* __restrict__ off,
                                                     int* __restrict__ bsum, int n) {
    __shared__ int s[1024];
    int tid = threadIdx.x;
    int gi = blockIdx.x * 1024 + tid;
    int v = (gi < n) ? deg[gi] : 0;
    s[tid] = v;
    __syncthreads();
    for (int d = 1; d < 1024; d <<= 1) {
        int t = (tid >= d) ? s[tid - d] : 0;
        __syncthreads();
        if (tid >= d) s[tid] += t;
        __syncthreads();
    }
    if (gi < n) off[gi] = s[tid] - v;
    if (tid == 1023) bsum[blockIdx.x] = s[1023];
}

__global__ void scan2_kernel(int* __restrict__ bsum, int nb) {
    if (threadIdx.x == 0) {
        int acc = 0;
        for (int i = 0; i < nb; i++) {
            int v = bsum[i];
            bsum[i] = acc;
            acc += v;
        }
    }
}

__global__ void scan3_kernel(int* __restrict__ off, const int* __restrict__ bsum, int n) {
    int i = blockIdx.x * blockDim.x + threadIdx.x;
    if (i < n) off[i] += bsum[i >> 10];
}

__global__ void scatter_kernel(const int* __restrict__ ei, const int* __restrict__ off,
                               int* __restrict__ cur, int* __restrict__ eperm,
                               int* __restrict__ sperm, int E) {
    int e = blockIdx.x * blockDim.x + threadIdx.x;
    if (e >= E) return;
    int d = ei[E + e];
    int pos = off[d] + atomicAdd(&cur[d], 1);
    eperm[pos] = e;
    sperm[pos] = ei[e];
}

// ------- message + aggregate: z = h + sum relu(hb[src]+e); e CSR-sequential --------
__global__ __launch_bounds__(256) void aggregate_kernel(
    const float* __restrict__ h, const __half* __restrict__ hb,
    const __half* __restrict__ e,
    const int* __restrict__ off, const int* __restrict__ deg,
    const int* __restrict__ sperm,
    float* __restrict__ z, int n) {
    int w = (blockIdx.x * blockDim.x + threadIdx.x) >> 5;
    int lane = threadIdx.x & 31;
    if (w >= n) return;
    const float4* h4 = reinterpret_cast<const float4*>(h);
    const uint2* e2 = reinterpret_cast<const uint2*>(e);
    const uint2* hb2 = reinterpret_cast<const uint2*>(hb);
    float4 acc = h4[w * 32 + lane];
    int j = off[w];
    const int jend = j + deg[w];
#define ACCUM(ev, hv) do { \
    float2 fa = __half22float2(*reinterpret_cast<__half2*>(&(ev).x)); \
    float2 fb = __half22float2(*reinterpret_cast<__half2*>(&(ev).y)); \
    float2 ga = __half22float2(*reinterpret_cast<__half2*>(&(hv).x)); \
    float2 gb = __half22float2(*reinterpret_cast<__half2*>(&(hv).y)); \
    acc.x += fmaxf(fa.x + ga.x, 0.f); \
    acc.y += fmaxf(fa.y + ga.y, 0.f); \
    acc.z += fmaxf(fb.x + gb.x, 0.f); \
    acc.w += fmaxf(fb.y + gb.y, 0.f); } while (0)
    for (; j + 3 < jend; j += 4) {
        int s0 = sperm[j], s1 = sperm[j + 1], s2 = sperm[j + 2], s3 = sperm[j + 3];
        uint2 ev0 = __ldcs(&e2[(size_t)j * 32 + lane]);
        uint2 hv0 = hb2[(size_t)s0 * 32 + lane];
        uint2 ev1 = __ldcs(&e2[(size_t)(j + 1) * 32 + lane]);
        uint2 hv1 = hb2[(size_t)s1 * 32 + lane];
        uint2 ev2 = __ldcs(&e2[(size_t)(j + 2) * 32 + lane]);
        uint2 hv2 = hb2[(size_t)s2 * 32 + lane];
        uint2 ev3 = __ldcs(&e2[(size_t)(j + 3) * 32 + lane]);
        uint2 hv3 = hb2[(size_t)s3 * 32 + lane];
        ACCUM(ev0, hv0);
        ACCUM(ev1, hv1);
        ACCUM(ev2, hv2);
        ACCUM(ev3, hv3);
    }
    for (; j < jend; j++) {
        int s0 = sperm[j];
        uint2 ev0 = __ldcs(&e2[(size_t)j * 32 + lane]);
        uint2 hv0 = hb2[(size_t)s0 * 32 + lane];
        ACCUM(ev0, hv0);
    }
#undef ACCUM
    reinterpret_cast<float4*>(z)[w * 32 + lane] = acc;
}

// ---------------- pooling ----------------
__global__ void gate2_kernel(const float* __restrict__ hid, const float* __restrict__ w2,
                             const float* __restrict__ b2, float* __restrict__ gate, int n) {
    int w = (blockIdx.x * blockDim.x + threadIdx.x) >> 5;
    int lane = threadIdx.x & 31;
    if (w >= n) return;
    float s = hid[w * 64 + lane] * w2[lane] + hid[w * 64 + 32 + lane] * w2[32 + lane];
#pragma unroll
    for (int o = 16; o > 0; o >>= 1) s += __shfl_down_sync(0xffffffffu, s, o);
    if (lane == 0) gate[w] = s + b2[0];
}

__device__ __forceinline__ unsigned f2ord(float f) {
    unsigned b = __float_as_uint(f);
    return (b & 0x80000000u) ? ~b : (b | 0x80000000u);
}
__device__ __forceinline__ float ord2f(unsigned k) {
    return __uint_as_float((k & 0x80000000u) ? (k & 0x7fffffffu) : ~k);
}

__global__ void smax_kernel(const float* __restrict__ gate, const int* __restrict__ batch,
                            unsigned* __restrict__ gmaxk, int n) {
    int i = blockIdx.x * blockDim.x + threadIdx.x;
    if (i < n) atomicMax(&gmaxk[batch[i]], f2ord(gate[i]));
}

__global__ void wexp_kernel(const float* __restrict__ gate, const int* __restrict__ batch,
                            const unsigned* __restrict__ gmaxk, float* __restrict__ wexp,
                            float* __restrict__ den, int n) {
    int i = blockIdx.x * blockDim.x + threadIdx.x;
    if (i >= n) return;
    float m = ord2f(gmaxk[batch[i]]);
    float w = expf(gate[i] - m);
    wexp[i] = w;
    atomicAdd(&den[batch[i]], w);
}

// run-length pool: batch is sorted; warp walks 64 consecutive nodes,
// accumulates alpha*h in registers, flushes atomics only on graph change.
#define PCH 64
__global__ void pool_kernel(const float* __restrict__ h, const int* __restrict__ batch,
                            const float* __restrict__ wexp, const float* __restrict__ den,
                            float* __restrict__ pool, int n) {
    int wg = (blockIdx.x * blockDim.x + threadIdx.x) >> 5;
    int lane = threadIdx.x & 31;
    int base = wg * PCH;
    if (base >= n) return;
    int end = min(base + PCH, n);
    const float4* h4 = reinterpret_cast<const float4*>(h);
    int curb = -1;
    float4 acc = make_float4(0.f, 0.f, 0.f, 0.f);
    for (int node = base; node < end; node++) {
        int b = batch[node];
        if (b != curb) {
            if (curb >= 0) {
                float* p = pool + curb * HH + lane * 4;
                atomicAdd(p + 0, acc.x);
                atomicAdd(p + 1, acc.y);
                atomicAdd(p + 2, acc.z);
                atomicAdd(p + 3, acc.w);
            }
            curb = b;
            acc = make_float4(0.f, 0.f, 0.f, 0.f);
        }
        float alpha = wexp[node] / den[b];
        float4 hv = h4[(size_t)node * 32 + lane];
        acc.x += alpha * hv.x;
        acc.y += alpha * hv.y;
        acc.z += alpha * hv.z;
        acc.w += alpha * hv.w;
    }
    if (curb >= 0) {
        float* p = pool + curb * HH + lane * 4;
        atomicAdd(p + 0, acc.x);
        atomicAdd(p + 1, acc.y);
        atomicAdd(p + 2, acc.z);
        atomicAdd(p + 3, acc.w);
    }
}

__global__ void head2_kernel(const float* __restrict__ ht, const float* __restrict__ w2,
                             const float* __restrict__ b2, float* __restrict__ out,
                             int G, int T) {
    int i = blockIdx.x * blockDim.x + threadIdx.x;
    if (i >= G * T) return;
    int g = i / T, t = i - g * T;
    float s = b2[t];
    for (int k = 0; k < HH; k++) s += ht[g * HH + k] * w2[k * T + t];
    out[i] = s;
}

// ---------------- launch ----------------
extern "C" void kernel_launch(void* const* d_in, const int* in_sizes, int n_in,
                              void* d_out, int out_size) {
    const float* x = (const float*)d_in[0];
    const float* edge_attr = (const float*)d_in[1];
    const float* node_w = (const float*)d_in[2];
    const float* node_b = (const float*)d_in[3];
    const float* edge_w1 = (const float*)d_in[4];
    const float* edge_b1 = (const float*)d_in[5];
    const float* edge_w2 = (const float*)d_in[6];
    const float* edge_b2 = (const float*)d_in[7];
    const float* conv_w1 = (const float*)d_in[8];
    const float* conv_b1 = (const float*)d_in[9];
    const float* conv_w2 = (const float*)d_in[10];
    const float* conv_b2 = (const float*)d_in[11];
    const float* bn_gamma = (const float*)d_in[12];
    const float* bn_beta = (const float*)d_in[13];
    const float* gate_w1 = (const float*)d_in[14];
    const float* gate_b1 = (const float*)d_in[15];
    const float* gate_w2 = (const float*)d_in[16];
    const float* gate_b2 = (const float*)d_in[17];
    const float* head_w1 = (const float*)d_in[18];
    const float* head_b1 = (const float*)d_in[19];
    const float* head_w2 = (const float*)d_in[20];
    const float* head_b2 = (const float*)d_in[21];
    const int* edge_index = (const int*)d_in[22];
    const int* batch = (const int*)d_in[23];

    const int N = in_sizes[0] / 64;
    const int E = in_sizes[22] / 2;
    const int T = 5;
    const int G = out_size / T;

    float *h, *z, *tb, *gate, *wexp, *den, *pool, *ht;
    __half *e, *hb;
    int *deg, *off, *cur, *bsum, *eperm, *sperm;
    unsigned* gmaxk;
    cudaGetSymbolAddress((void**)&h, g_h);
    cudaGetSymbolAddress((void**)&hb, g_hb);
    cudaGetSymbolAddress((void**)&z, g_z);
    cudaGetSymbolAddress((void**)&tb, g_tb);
    cudaGetSymbolAddress((void**)&e, g_e);
    cudaGetSymbolAddress((void**)&deg, g_deg);
    cudaGetSymbolAddress((void**)&off, g_off);
    cudaGetSymbolAddress((void**)&cur, g_cur);
    cudaGetSymbolAddress((void**)&bsum, g_bsum);
    cudaGetSymbolAddress((void**)&eperm, g_eperm);
    cudaGetSymbolAddress((void**)&sperm, g_sperm);
    cudaGetSymbolAddress((void**)&gate, g_gate);
    cudaGetSymbolAddress((void**)&wexp, g_wexp);
    cudaGetSymbolAddress((void**)&gmaxk, g_gmaxk);
    cudaGetSymbolAddress((void**)&den, g_den);
    cudaGetSymbolAddress((void**)&pool, g_pool);
    cudaGetSymbolAddress((void**)&ht, g_ht);

    __half *wnh, *wnl, *c1h, *c1l, *c2h, *c2l, *wgh, *wgl, *whh, *whl,
        *e1h, *e1l, *e2h, *e2l;
    cudaGetSymbolAddress((void**)&wnh, g_wnh); cudaGetSymbolAddress((void**)&wnl, g_wnl);
    cudaGetSymbolAddress((void**)&c1h, g_c1h); cudaGetSymbolAddress((void**)&c1l, g_c1l);
    cudaGetSymbolAddress((void**)&c2h, g_c2h); cudaGetSymbolAddress((void**)&c2l, g_c2l);
    cudaGetSymbolAddress((void**)&wgh, g_wgh); cudaGetSymbolAddress((void**)&wgl, g_wgl);
    cudaGetSymbolAddress((void**)&whh, g_whh); cudaGetSymbolAddress((void**)&whl, g_whl);
    cudaGetSymbolAddress((void**)&e1h, g_e1h); cudaGetSymbolAddress((void**)&e1l, g_e1l);
    cudaGetSymbolAddress((void**)&e2h, g_e2h); cudaGetSymbolAddress((void**)&e2l, g_e2l);

    // dynamic smem sizes (bytes)
    const int SM_N1 = (2 * 128 * 72 + 2 * 64 * 136) * 2;
    const int SM_G = (2 * 128 * 136 + 2 * 128 * 72) * 2;
    const int SM_H = (2 * 128 * 136 + 2 * 128 * 136) * 2;
    const int SM_CONV = 6 * 128 * 136 * 2;
    const int SM_EDGE = (128 * 24 + 2 * 16 * 136 + 3 * 128 * 136) * 2;
    cudaFuncSetAttribute(mma_gemm<64, 128, false, true>, cudaFuncAttributeMaxDynamicSharedMemorySize, SM_N1);
    cudaFuncSetAttribute(mma_gemm<128, 64, true, false>, cudaFuncAttributeMaxDynamicSharedMemorySize, SM_G);
    cudaFuncSetAttribute(mma_gemm<128, 128, true, false>, cudaFuncAttributeMaxDynamicSharedMemorySize, SM_H);
    cudaFuncSetAttribute(conv_fused_kernel, cudaFuncAttributeMaxDynamicSharedMemorySize, SM_CONV);
    cudaFuncSetAttribute(edge_mma_kernel, cudaFuncAttributeMaxDynamicSharedMemorySize, SM_EDGE);

    // zero scratch
    cudaMemsetAsync(deg, 0, (size_t)N * 4, 0);
    cudaMemsetAsync(cur, 0, (size_t)N * 4, 0);
    cudaMemsetAsync(gmaxk, 0, (size_t)G * 4, 0);
    cudaMemsetAsync(den, 0, (size_t)G * 4, 0);
    cudaMemsetAsync(pool, 0, (size_t)G * HH * 4, 0);

    // fused weight prep: 13 segments, one launch
    PrepArgs pa{};
    int idx = 0, woff = 0;
    auto addseg = [&](const float* s, __half* hi, __half* lo, int K, int Nn, int PB) {
        pa.a[idx].src = s; pa.a[idx].hi = hi; pa.a[idx].lo = lo;
        pa.a[idx].N = Nn; pa.a[idx].PB = PB; pa.a[idx].start = woff; pa.a[idx].count = K * PB;
        woff += K * PB; idx++;
    };
    addseg(node_w, wnh, wnl, 64, 128, 136);
    for (int l = 0; l < 4; l++)
        addseg(conv_w1 + (size_t)l * 16384, c1h + (size_t)l * 128 * 136,
               c1l + (size_t)l * 128 * 136, 128, 128, 136);
    for (int l = 0; l < 4; l++)
        addseg(conv_w2 + (size_t)l * 16384, c2h + (size_t)l * 128 * 136,
               c2l + (size_t)l * 128 * 136, 128, 128, 136);
    addseg(gate_w1, wgh, wgl, 128, 64, 72);
    addseg(head_w1, whh, whl, 128, 128, 136);
    addseg(edge_w1, e1h, e1l, 16, 128, 136);
    addseg(edge_w2, e2h, e2l, 128, 128, 136);
    pa.total = woff;
    wprep_kernel<<<(pa.total + 255) / 256, 256>>>(pa);

    // CSR by dst (multi-block scan); eperm: CSR slot -> edge id
    const int NB = (N + 1023) / 1024;
    hist_kernel<<<(E + 255) / 256, 256>>>(edge_index, deg, E);
    scan1_kernel<<<NB, 1024>>>(deg, off, bsum, N);
    scan2_kernel<<<1, 32>>>(bsum, NB);
    scan3_kernel<<<(N + 255) / 256, 256>>>(off, bsum, N);
    scatter_kernel<<<(E + 255) / 256, 256>>>(edge_index, off, cur, eperm, sperm, E);

    // encoders (edge encoder gathers ea via eperm, writes e sequentially)
    mma_gemm<64, 128, false, true><<<(N + 127) / 128, 256, SM_N1>>>(
        x, wnh, wnl, node_b, h, hb, N);
    edge_mma_kernel<<<(E + 127) / 128, 256, SM_EDGE>>>(
        edge_attr, e1h, e1l, e2h, e2l, edge_b1, edge_b2, eperm, e, E);

    // 4 GINE layers: aggregate (CSR-streamed e) -> fused 2-GEMM conv
    for (int l = 0; l < 4; l++) {
        aggregate_kernel<<<(N + 7) / 8, 256>>>(h, hb, e, off, deg, sperm, z, N);
        conv_fused_kernel<<<(N + 127) / 128, 256, SM_CONV>>>(
            z, c1h + (size_t)l * 128 * 136, c1l + (size_t)l * 128 * 136,
            c2h + (size_t)l * 128 * 136, c2l + (size_t)l * 128 * 136,
            conv_b1 + l * HH, conv_b2 + l * HH,
            bn_gamma + l * HH, bn_beta + l * HH, h, hb, N);
    }

    // gate MLP + segment softmax pooling
    mma_gemm<128, 64, true, false><<<(N + 127) / 128, 256, SM_G>>>(
        h, wgh, wgl, gate_b1, tb, nullptr, N);
    gate2_kernel<<<(N + 7) / 8, 256>>>(tb, gate_w2, gate_b2, gate, N);
    smax_kernel<<<(N + 255) / 256, 256>>>(gate, batch, gmaxk, N);
    wexp_kernel<<<(N + 255) / 256, 256>>>(gate, batch, gmaxk, wexp, den, N);
    {
        int warps = (N + PCH - 1) / PCH;
        pool_kernel<<<(warps * 32 + 255) / 256, 256>>>(h, batch, wexp, den, pool, N);
    }

    // head
    mma_gemm<128, 128, true, false><<<(G + 127) / 128, 256, SM_H>>>(
        pool, whh, whl, head_b1, ht, nullptr, G);
    head2_kernel<<<(G * T + 255) / 256, 256>>>(ht, head_w2, head_b2, (float*)d_out, G, T);
}

// round 17
// speedup vs baseline: 1.2861x; 1.2861x over previous
#include <cuda_runtime.h>
#include <cuda_fp16.h>
#include <cstdint>

#define NN 50000
#define EE 640000
#define GGR 256
#define HH 128

// ---------------- scratch (device globals; no allocs allowed) ----------------
__device__ __align__(16) float g_h[NN * HH];
__device__ __align__(16) __half g_hb[NN * HH];
__device__ __align__(16) float g_z[NN * HH];
__device__ __align__(16) float g_tb[NN * HH];
__device__ __align__(16) __half g_e[(size_t)EE * HH];   // edge-id order
__device__ int g_deg[NN];
__device__ int g_off[NN];
__device__ int g_cur[NN];
__device__ int g_bsum[64];
__device__ int g_eperm[EE];   // CSR slot -> edge id
__device__ int g_sperm[EE];   // CSR slot -> src node
__device__ float g_gate[NN];
__device__ float g_wexp[NN];
__device__ unsigned g_gmaxk[GGR];
__device__ float g_den[GGR];
__device__ __align__(16) float g_pool[GGR * HH];
__device__ __align__(16) float g_ht[GGR * HH];

// split-fp16 weights (hi/lo), [K][N] row-major with padded pitch
__device__ __align__(16) __half g_wnh[64 * 136],  g_wnl[64 * 136];
__device__ __align__(16) __half g_c1h[4 * 128 * 136], g_c1l[4 * 128 * 136];
__device__ __align__(16) __half g_c2h[4 * 128 * 136], g_c2l[4 * 128 * 136];
__device__ __align__(16) __half g_wgh[128 * 72],  g_wgl[128 * 72];
__device__ __align__(16) __half g_whh[128 * 136], g_whl[128 * 136];
__device__ __align__(16) __half g_e1h[16 * 136],  g_e1l[16 * 136];
__device__ __align__(16) __half g_e2h[128 * 136], g_e2l[128 * 136];

// ---------------- helpers ----------------
__device__ __forceinline__ uint32_t smem_u32(const void* p) {
    uint32_t a;
    asm("{ .reg .u64 t; cvta.to.shared.u64 t, %1; cvt.u32.u64 %0, t; }" : "=r"(a) : "l"(p));
    return a;
}
__device__ __forceinline__ uint32_t h2pack(float a, float b) {
    __half2 v = __floats2half2_rn(a, b);
    return *reinterpret_cast<uint32_t*>(&v);
}
__device__ __forceinline__ void wsplit(float x, __half& h, __half& l) {
    h = __float2half_rn(x);
    l = __float2half_rn(x - __half2float(h));
}
__device__ __forceinline__ void split2pack(float a, float b, uint32_t& hi, uint32_t& lo) {
    __half ha, la, hb_, lb;
    wsplit(a, ha, la);
    wsplit(b, hb_, lb);
    __half2 vh = __halves2half2(ha, hb_);
    __half2 vl = __halves2half2(la, lb);
    hi = *reinterpret_cast<uint32_t*>(&vh);
    lo = *reinterpret_cast<uint32_t*>(&vl);
}

__device__ __forceinline__ void ldsm_x4(uint32_t* r, uint32_t addr) {
    asm volatile("ldmatrix.sync.aligned.m8n8.x4.shared.b16 {%0,%1,%2,%3}, [%4];"
                 : "=r"(r[0]), "=r"(r[1]), "=r"(r[2]), "=r"(r[3]) : "r"(addr));
}
__device__ __forceinline__ void ldsm_x4t(uint32_t* r, uint32_t addr) {
    asm volatile("ldmatrix.sync.aligned.m8n8.x4.trans.shared.b16 {%0,%1,%2,%3}, [%4];"
                 : "=r"(r[0]), "=r"(r[1]), "=r"(r[2]), "=r"(r[3]) : "r"(addr));
}
__device__ __forceinline__ void mma16816(float* d, const uint32_t* a, const uint32_t* b) {
    asm volatile(
        "mma.sync.aligned.m16n8k16.row.col.f32.f16.f16.f32 "
        "{%0,%1,%2,%3}, {%4,%5,%6,%7}, {%8,%9}, {%0,%1,%2,%3};"
        : "+f"(d[0]), "+f"(d[1]), "+f"(d[2]), "+f"(d[3])
        : "r"(a[0]), "r"(a[1]), "r"(a[2]), "r"(a[3]), "r"(b[0]), "r"(b[1]));
}

// ---------------- fused weight prep: all 13 segments in one launch ----------------
struct PrepArg {
    const float* src;
    __half* hi;
    __half* lo;
    int N, PB, start, count;
};
struct PrepArgs {
    PrepArg a[13];
    int total;
};

__global__ void wprep_kernel(PrepArgs p) {
    int i = blockIdx.x * blockDim.x + threadIdx.x;
    if (i >= p.total) return;
#pragma unroll
    for (int s = 0; s < 13; s++) {
        if (i < p.a[s].start + p.a[s].count) {
            int local = i - p.a[s].start;
            int k = local / p.a[s].PB, n = local - k * p.a[s].PB;
            float x = (n < p.a[s].N) ? p.a[s].src[(size_t)k * p.a[s].N + n] : 0.f;
            __half h, l;
            wsplit(x, h, l);
            p.a[s].hi[local] = h;
            p.a[s].lo[local] = l;
            return;
        }
    }
}

// -------- 3-term tensor-core GEMM: C = op((Ah+Al) @ (Wh+Wl) + b), drop Al*Wl -------
template <int K, int NC, bool RELU, bool F16OUT>
__global__ void __launch_bounds__(256) mma_gemm(
    const float* __restrict__ A, const __half* __restrict__ Bhi,
    const __half* __restrict__ Blo, const float* __restrict__ bias,
    float* __restrict__ C, __half* __restrict__ Cb, int M) {
    constexpr int PA = K + 8;
    constexpr int PB = NC + 8;
    constexpr int NF = NC / 16;
    extern __shared__ __align__(16) char smc[];
    __half* Ah = (__half*)smc;
    __half* Al = Ah + 128 * PA;
    __half* Bh = Al + 128 * PA;
    __half* Bl = Bh + K * PB;

    const int tid = threadIdx.x;
    const int lane = tid & 31, w = tid >> 5;
    const int wm = (w & 3) * 32;
    const int wn = (w >> 2) * (NC / 2);
    const int m0 = blockIdx.x * 128;

    {
        const float4* sh = (const float4*)Bhi;
        const float4* sl = (const float4*)Blo;
        float4* dh = (float4*)Bh;
        float4* dl = (float4*)Bl;
        for (int i = tid; i < K * PB / 8; i += 256) { dh[i] = sh[i]; dl[i] = sl[i]; }
    }
    {
        int r = tid >> 1, half_ = tid & 1;
        int gr = m0 + r;
        bool v = gr < M;
        const float4* a4 = (const float4*)(A + (size_t)gr * K) + half_ * (K / 8);
        __half* th = Ah + r * PA + half_ * (K / 2);
        __half* tl = Al + r * PA + half_ * (K / 2);
#pragma unroll
        for (int i = 0; i < K / 8; i++) {
            float4 x = v ? a4[i] : make_float4(0.f, 0.f, 0.f, 0.f);
            uint32_t h0, l0, h1, l1;
            split2pack(x.x, x.y, h0, l0);
            split2pack(x.z, x.w, h1, l1);
            *(uint32_t*)(th + i * 4) = h0;
            *(uint32_t*)(th + i * 4 + 2) = h1;
            *(uint32_t*)(tl + i * 4) = l0;
            *(uint32_t*)(tl + i * 4 + 2) = l1;
        }
    }
    __syncthreads();

    float acc[2][NF][4];
#pragma unroll
    for (int i = 0; i < 2; i++)
#pragma unroll
        for (int j = 0; j < NF; j++)
#pragma unroll
            for (int q = 0; q < 4; q++) acc[i][j][q] = 0.f;

    const uint32_t Ahb = smem_u32(Ah), Alb = smem_u32(Al);
    const uint32_t Bhb = smem_u32(Bh), Blb = smem_u32(Bl);
    const int a_row = lane & 15, a_kof = (lane >> 4) << 3;
    const int b_mat = lane >> 3, b_r = lane & 7;
    const int b_krow = ((b_mat & 1) << 3) + b_r;
    const int b_ncol = (b_mat >> 1) << 3;

#pragma unroll
    for (int ks = 0; ks < K / 16; ks++) {
        const int k0 = ks * 16;
        uint32_t ahf[2][4], alf[2][4];
#pragma unroll
        for (int mi = 0; mi < 2; mi++) {
            uint32_t off = ((wm + mi * 16 + a_row) * PA + k0 + a_kof) * 2;
            ldsm_x4(ahf[mi], Ahb + off);
            ldsm_x4(alf[mi], Alb + off);
        }
#pragma unroll
        for (int np = 0; np < NF / 2; np++) {
            uint32_t off = ((k0 + b_krow) * PB + wn + np * 16 + b_ncol) * 2;
            uint32_t bhf[4], blf[4];
            ldsm_x4t(bhf, Bhb + off);
            ldsm_x4t(blf, Blb + off);
#pragma unroll
            for (int mi = 0; mi < 2; mi++) {
                mma16816(acc[mi][2 * np], ahf[mi], bhf);
                mma16816(acc[mi][2 * np], ahf[mi], blf);
                mma16816(acc[mi][2 * np], alf[mi], bhf);
                mma16816(acc[mi][2 * np + 1], ahf[mi], bhf + 2);
                mma16816(acc[mi][2 * np + 1], ahf[mi], blf + 2);
                mma16816(acc[mi][2 * np + 1], alf[mi], bhf + 2);
            }
        }
    }

    const int rbase = m0 + wm + (lane >> 2);
    const int cbase = wn + (lane & 3) * 2;
#pragma unroll
    for (int mi = 0; mi < 2; mi++) {
#pragma unroll
        for (int nj = 0; nj < NF; nj++) {
            int col = cbase + nj * 8;
            float b0 = bias[col], b1v = bias[col + 1];
#pragma unroll
            for (int hh = 0; hh < 2; hh++) {
                int row = rbase + mi * 16 + hh * 8;
                if (row < M) {
                    float v0 = acc[mi][nj][hh * 2 + 0] + b0;
                    float v1 = acc[mi][nj][hh * 2 + 1] + b1v;
                    if (RELU) { v0 = fmaxf(v0, 0.f); v1 = fmaxf(v1, 0.f); }
                    *(float2*)(C + (size_t)row * NC + col) = make_float2(v0, v1);
                    if (F16OUT)
                        *(uint32_t*)(Cb + (size_t)row * NC + col) = h2pack(v0, v1);
                }
            }
        }
    }
}

// ---------------- fused conv layer: h' = relu(BN(relu(z@W1)@W2)) -------------------
__global__ void __launch_bounds__(256) conv_fused_kernel(
    const float* __restrict__ Z,
    const __half* __restrict__ W1h, const __half* __restrict__ W1l,
    const __half* __restrict__ W2h, const __half* __restrict__ W2l,
    const float* __restrict__ b1, const float* __restrict__ b2,
    const float* __restrict__ gamma, const float* __restrict__ beta,
    float* __restrict__ Hout, __half* __restrict__ HBout, int M) {
    constexpr int PW = 136;
    extern __shared__ __align__(16) char smc[];
    __half* As = (__half*)smc;
    __half* Al = As + 128 * PW;
    __half* Q1h = Al + 128 * PW;
    __half* Q1l = Q1h + 128 * PW;
    __half* Q2h = Q1l + 128 * PW;
    __half* Q2l = Q2h + 128 * PW;

    const int tid = threadIdx.x;
    const int lane = tid & 31, w = tid >> 5;
    const int wm = (w & 3) * 32;
    const int wn = (w >> 2) * 64;
    const int m0 = blockIdx.x * 128;

    {
        const float4* s1h = (const float4*)W1h; const float4* s1l = (const float4*)W1l;
        const float4* s2h = (const float4*)W2h; const float4* s2l = (const float4*)W2l;
        float4* d1h = (float4*)Q1h; float4* d1l = (float4*)Q1l;
        float4* d2h = (float4*)Q2h; float4* d2l = (float4*)Q2l;
        for (int i = tid; i < 128 * PW / 8; i += 256) {
            d1h[i] = s1h[i]; d1l[i] = s1l[i];
            d2h[i] = s2h[i]; d2l[i] = s2l[i];
        }
    }
    {
        int r = tid >> 1, half_ = tid & 1;
        int gr = m0 + r;
        bool v = gr < M;
        const float4* a4 = (const float4*)(Z + (size_t)gr * 128) + half_ * 16;
        __half* th = As + r * PW + half_ * 64;
        __half* tl = Al + r * PW + half_ * 64;
#pragma unroll
        for (int i = 0; i < 16; i++) {
            float4 x = v ? a4[i] : make_float4(0.f, 0.f, 0.f, 0.f);
            uint32_t h0, l0, h1, l1;
            split2pack(x.x, x.y, h0, l0);
            split2pack(x.z, x.w, h1, l1);
            *(uint32_t*)(th + i * 4) = h0;
            *(uint32_t*)(th + i * 4 + 2) = h1;
            *(uint32_t*)(tl + i * 4) = l0;
            *(uint32_t*)(tl + i * 4 + 2) = l1;
        }
    }
    __syncthreads();

    const uint32_t Asb = smem_u32(As), Alb = smem_u32(Al);
    const uint32_t Q1hb = smem_u32(Q1h), Q1lb = smem_u32(Q1l);
    const uint32_t Q2hb = smem_u32(Q2h), Q2lb = smem_u32(Q2l);
    const int a_row = lane & 15, a_kof = (lane >> 4) << 3;
    const int b_mat = lane >> 3, b_r = lane & 7;
    const int b_krow = ((b_mat & 1) << 3) + b_r;
    const int b_ncol = (b_mat >> 1) << 3;
    const int frow = lane >> 2, fcol = (lane & 3) * 2;

    float acc[2][8][4];
#pragma unroll
    for (int i = 0; i < 2; i++)
#pragma unroll
        for (int j = 0; j < 8; j++)
#pragma unroll
            for (int q = 0; q < 4; q++) acc[i][j][q] = 0.f;

    // ---- phase 1: hidden = z @ W1 (3-term) ----
#pragma unroll
    for (int ks = 0; ks < 8; ks++) {
        const int k0 = ks * 16;
        uint32_t ahf[2][4], alf[2][4];
#pragma unroll
        for (int mi = 0; mi < 2; mi++) {
            uint32_t o = ((wm + mi * 16 + a_row) * PW + k0 + a_kof) * 2;
            ldsm_x4(ahf[mi], Asb + o);
            ldsm_x4(alf[mi], Alb + o);
        }
#pragma unroll
        for (int np = 0; np < 4; np++) {
            uint32_t o = ((k0 + b_krow) * PW + wn + np * 16 + b_ncol) * 2;
            uint32_t bhf[4], blf[4];
            ldsm_x4t(bhf, Q1hb + o);
            ldsm_x4t(blf, Q1lb + o);
#pragma unroll
            for (int mi = 0; mi < 2; mi++) {
                mma16816(acc[mi][2 * np], ahf[mi], bhf);
                mma16816(acc[mi][2 * np], ahf[mi], blf);
                mma16816(acc[mi][2 * np], alf[mi], bhf);
                mma16816(acc[mi][2 * np + 1], ahf[mi], bhf + 2);
                mma16816(acc[mi][2 * np + 1], ahf[mi], blf + 2);
                mma16816(acc[mi][2 * np + 1], alf[mi], bhf + 2);
            }
        }
    }
    __syncthreads();

    // relu(acc+b1) -> split back into As/Al
#pragma unroll
    for (int mi = 0; mi < 2; mi++) {
#pragma unroll
        for (int nj = 0; nj < 8; nj++) {
            int col = wn + nj * 8 + fcol;
            float c0 = b1[col], c1 = b1[col + 1];
#pragma unroll
            for (int hh = 0; hh < 2; hh++) {
                int row = wm + mi * 16 + hh * 8 + frow;
                float v0 = fmaxf(acc[mi][nj][hh * 2 + 0] + c0, 0.f);
                float v1 = fmaxf(acc[mi][nj][hh * 2 + 1] + c1, 0.f);
                uint32_t ph, pl;
                split2pack(v0, v1, ph, pl);
                *(uint32_t*)(As + row * PW + col) = ph;
                *(uint32_t*)(Al + row * PW + col) = pl;
            }
        }
    }
    __syncthreads();

    // ---- phase 2: out = hidden @ W2 (3-term) ----
#pragma unroll
    for (int i = 0; i < 2; i++)
#pragma unroll
        for (int j = 0; j < 8; j++)
#pragma unroll
            for (int q = 0; q < 4; q++) acc[i][j][q] = 0.f;
#pragma unroll
    for (int ks = 0; ks < 8; ks++) {
        const int k0 = ks * 16;
        uint32_t ahf[2][4], alf[2][4];
#pragma unroll
        for (int mi = 0; mi < 2; mi++) {
            uint32_t o = ((wm + mi * 16 + a_row) * PW + k0 + a_kof) * 2;
            ldsm_x4(ahf[mi], Asb + o);
            ldsm_x4(alf[mi], Alb + o);
        }
#pragma unroll
        for (int np = 0; np < 4; np++) {
            uint32_t o = ((k0 + b_krow) * PW + wn + np * 16 + b_ncol) * 2;
            uint32_t bhf[4], blf[4];
            ldsm_x4t(bhf, Q2hb + o);
            ldsm_x4t(blf, Q2lb + o);
#pragma unroll
            for (int mi = 0; mi < 2; mi++) {
                mma16816(acc[mi][2 * np], ahf[mi], bhf);
                mma16816(acc[mi][2 * np], ahf[mi], blf);
                mma16816(acc[mi][2 * np], alf[mi], bhf);
                mma16816(acc[mi][2 * np + 1], ahf[mi], bhf + 2);
                mma16816(acc[mi][2 * np + 1], ahf[mi], blf + 2);
                mma16816(acc[mi][2 * np + 1], alf[mi], bhf + 2);
            }
        }
    }

    const float bnsc = 0.99999500003749968f;
#pragma unroll
    for (int mi = 0; mi < 2; mi++) {
#pragma unroll
        for (int nj = 0; nj < 8; nj++) {
            int col = wn + nj * 8 + fcol;
            float c0 = b2[col], c1 = b2[col + 1];
            float g0 = bnsc * gamma[col], g1 = bnsc * gamma[col + 1];
            float t0 = beta[col], t1 = beta[col + 1];
#pragma unroll
            for (int hh = 0; hh < 2; hh++) {
                int row = m0 + wm + mi * 16 + hh * 8 + frow;
                if (row < M) {
                    float v0 = fmaxf((acc[mi][nj][hh * 2 + 0] + c0) * g0 + t0, 0.f);
                    float v1 = fmaxf((acc[mi][nj][hh * 2 + 1] + c1) * g1 + t1, 0.f);
                    *(float2*)(Hout + (size_t)row * 128 + col) = make_float2(v0, v1);
                    *(uint32_t*)(HBout + (size_t)row * 128 + col) = h2pack(v0, v1);
                }
            }
        }
    }
}

// ---- fused edge encoder (hi-only fp16): e = fp16(relu(ea@W1+b1)@W2+b2), seq write ----
__global__ void __launch_bounds__(256) edge_mma_kernel(
    const float* __restrict__ EA,
    const __half* __restrict__ W1h, const __half* __restrict__ W2h,
    const float* __restrict__ b1, const float* __restrict__ b2,
    __half* __restrict__ Eout, int E) {
    constexpr int PA1 = 24;
    constexpr int PW = 136;
    extern __shared__ __align__(16) char smc[];
    __half* A1 = (__half*)smc;         // 128*24
    __half* Q1 = A1 + 128 * PA1;       // 16*136
    __half* A2 = Q1 + 16 * PW;         // 128*136 (hidden)
    __half* Q2 = A2 + 128 * PW;        // 128*136

    const int tid = threadIdx.x;
    const int lane = tid & 31, w = tid >> 5;
    const int wm = (w & 3) * 32;
    const int wn = (w >> 2) * 64;
    const int m0 = blockIdx.x * 128;

    {
        const float4* s1 = (const float4*)W1h;
        const float4* s2 = (const float4*)W2h;
        float4* d1 = (float4*)Q1;
        float4* d2 = (float4*)Q2;
        for (int i = tid; i < 16 * PW / 8; i += 256) d1[i] = s1[i];
        for (int i = tid; i < 128 * PW / 8; i += 256) d2[i] = s2[i];
    }
    {
        int r = tid >> 1, half_ = tid & 1;
        int ge = m0 + r;
        bool v = ge < E;
        const float4* a4 = (const float4*)(EA + (size_t)ge * 16) + half_ * 2;
        __half* ts = A1 + r * PA1 + half_ * 8;
#pragma unroll
        for (int i = 0; i < 2; i++) {
            float4 x = v ? a4[i] : make_float4(0.f, 0.f, 0.f, 0.f);
            *(uint32_t*)(ts + i * 4) = h2pack(x.x, x.y);
            *(uint32_t*)(ts + i * 4 + 2) = h2pack(x.z, x.w);
        }
    }
    __syncthreads();

    const int a_row = lane & 15, a_kof = (lane >> 4) << 3;
    const int b_mat = lane >> 3, b_r = lane & 7;
    const int b_krow = ((b_mat & 1) << 3) + b_r;
    const int b_ncol = (b_mat >> 1) << 3;
    const int frow = lane >> 2, fcol = (lane & 3) * 2;
    const uint32_t A1b = smem_u32(A1), Q1b = smem_u32(Q1);
    const uint32_t A2b = smem_u32(A2), Q2b = smem_u32(Q2);

    float acc[2][8][4];
#pragma unroll
    for (int i = 0; i < 2; i++)
#pragma unroll
        for (int j = 0; j < 8; j++)
#pragma unroll
            for (int q = 0; q < 4; q++) acc[i][j][q] = 0.f;

    // phase 1: single k16 step (hi-only)
    {
        uint32_t af[2][4];
#pragma unroll
        for (int mi = 0; mi < 2; mi++)
            ldsm_x4(af[mi], A1b + ((wm + mi * 16 + a_row) * PA1 + a_kof) * 2);
#pragma unroll
        for (int np = 0; np < 4; np++) {
            uint32_t bf[4];
            ldsm_x4t(bf, Q1b + (b_krow * PW + wn + np * 16 + b_ncol) * 2);
#pragma unroll
            for (int mi = 0; mi < 2; mi++) {
                mma16816(acc[mi][2 * np], af[mi], bf);
                mma16816(acc[mi][2 * np + 1], af[mi], bf + 2);
            }
        }
    }
#pragma unroll
    for (int mi = 0; mi < 2; mi++) {
#pragma unroll
        for (int nj = 0; nj < 8; nj++) {
            int col = wn + nj * 8 + fcol;
            float c0 = b1[col], c1 = b1[col + 1];
#pragma unroll
            for (int hh = 0; hh < 2; hh++) {
                int row = wm + mi * 16 + hh * 8 + frow;
                float v0 = fmaxf(acc[mi][nj][hh * 2 + 0] + c0, 0.f);
                float v1 = fmaxf(acc[mi][nj][hh * 2 + 1] + c1, 0.f);
                *(uint32_t*)(A2 + row * PW + col) = h2pack(v0, v1);
            }
        }
    }
    __syncthreads();

    // phase 2: e = hidden @ W2, K=128 (hi-only)
#pragma unroll
    for (int i = 0; i < 2; i++)
#pragma unroll
        for (int j = 0; j < 8; j++)
#pragma unroll
            for (int q = 0; q < 4; q++) acc[i][j][q] = 0.f;
#pragma unroll
    for (int ks = 0; ks < 8; ks++) {
        const int k0 = ks * 16;
        uint32_t af[2][4];
#pragma unroll
        for (int mi = 0; mi < 2; mi++)
            ldsm_x4(af[mi], A2b + ((wm + mi * 16 + a_row) * PW + k0 + a_kof) * 2);
#pragma unroll
        for (int np = 0; np < 4; np++) {
            uint32_t bf[4];
            ldsm_x4t(bf, Q2b + ((k0 + b_krow) * PW + wn + np * 16 + b_ncol) * 2);
#pragma unroll
            for (int mi = 0; mi < 2; mi++) {
                mma16816(acc[mi][2 * np], af[mi], bf);
                mma16816(acc[mi][2 * np + 1], af[mi], bf + 2);
            }
        }
    }
    // epilogue: sequential edge-id rows
#pragma unroll
    for (int mi = 0; mi < 2; mi++) {
#pragma unroll
        for (int nj = 0; nj < 8; nj++) {
            int col = wn + nj * 8 + fcol;
            float c0 = b2[col], c1 = b2[col + 1];
#pragma unroll
            for (int hh = 0; hh < 2; hh++) {
                int row = m0 + wm + mi * 16 + hh * 8 + frow;
                if (row < E) {
                    *(uint32_t*)(Eout + (size_t)row * 128 + col) =
                        h2pack(acc[mi][nj][hh * 2 + 0] + c0,
                               acc[mi][nj][hh * 2 + 1] + c1);
                }
            }
        }
    }
}

// ---------------- CSR build ----------------
__global__ void hist_kernel(const int* __restrict__ ei, int* __restrict__ deg, int E) {
    int e = blockIdx.x * blockDim.x + threadIdx.x;
    if (e < E) atomicAdd(&deg[ei[E + e]], 1);
}

__global__ __launch_bounds__(1024) void scan1_kernel(const int* __restrict__ deg,
                                                     int* __restrict__ off,
                                                     int* __restrict__ bsum, int n) {
    __shared__ int s[1024];
    int tid = threadIdx.x;
    int gi = blockIdx.x * 1024 + tid;
    int v = (gi < n) ? deg[gi] : 0;
    s[tid] = v;
    __syncthreads();
    for (int d = 1; d < 1024; d <<= 1) {
        int t = (tid >= d) ? s[tid - d] : 0;
        __syncthreads();
        if (tid >= d) s[tid] += t;
        __syncthreads();
    }
    if (gi < n) off[gi] = s[tid] - v;
    if (tid == 1023) bsum[blockIdx.x] = s[1023];
}

__global__ void scan2_kernel(int* __restrict__ bsum, int nb) {
    if (threadIdx.x == 0) {
        int acc = 0;
        for (int i = 0; i < nb; i++) {
            int v = bsum[i];
            bsum[i] = acc;
            acc += v;
        }
    }
}

__global__ void scan3_kernel(int* __restrict__ off, const int* __restrict__ bsum, int n) {
    int i = blockIdx.x * blockDim.x + threadIdx.x;
    if (i < n) off[i] += bsum[i >> 10];
}

__global__ void scatter_kernel(const int* __restrict__ ei, const int* __restrict__ off,
                               int* __restrict__ cur, int* __restrict__ eperm,
                               int* __restrict__ sperm, int E) {
    int e = blockIdx.x * blockDim.x + threadIdx.x;
    if (e >= E) return;
    int d = ei[E + e];
    int pos = off[d] + atomicAdd(&cur[d], 1);
    eperm[pos] = e;
    sperm[pos] = ei[e];
}

// ------- message + aggregate: z = h + sum relu(hb[src]+e[eperm]) -------------------
__global__ __launch_bounds__(256) void aggregate_kernel(
    const float* __restrict__ h, const __half* __restrict__ hb,
    const __half* __restrict__ e,
    const int* __restrict__ off, const int* __restrict__ deg,
    const int* __restrict__ eperm, const int* __restrict__ sperm,
    float* __restrict__ z, int n) {
    int w = (blockIdx.x * blockDim.x + threadIdx.x) >> 5;
    int lane = threadIdx.x & 31;
    if (w >= n) return;
    const float4* h4 = reinterpret_cast<const float4*>(h);
    const uint2* e2 = reinterpret_cast<const uint2*>(e);
    const uint2* hb2 = reinterpret_cast<const uint2*>(hb);
    float4 acc = h4[w * 32 + lane];
    int j = off[w];
    const int jend = j + deg[w];
#define ACCUM(ev, hv) do { \
    float2 fa = __half22float2(*reinterpret_cast<__half2*>(&(ev).x)); \
    float2 fb = __half22float2(*reinterpret_cast<__half2*>(&(ev).y)); \
    float2 ga = __half22float2(*reinterpret_cast<__half2*>(&(hv).x)); \
    float2 gb = __half22float2(*reinterpret_cast<__half2*>(&(hv).y)); \
    acc.x += fmaxf(fa.x + ga.x, 0.f); \
    acc.y += fmaxf(fa.y + ga.y, 0.f); \
    acc.z += fmaxf(fb.x + gb.x, 0.f); \
    acc.w += fmaxf(fb.y + gb.y, 0.f); } while (0)
    for (; j + 3 < jend; j += 4) {
        int e0 = eperm[j], s0 = sperm[j];
        int e1 = eperm[j + 1], s1 = sperm[j + 1];
        int e2i = eperm[j + 2], s2 = sperm[j + 2];
        int e3 = eperm[j + 3], s3 = sperm[j + 3];
        uint2 ev0 = __ldcs(&e2[(size_t)e0 * 32 + lane]);
        uint2 hv0 = hb2[(size_t)s0 * 32 + lane];
        uint2 ev1 = __ldcs(&e2[(size_t)e1 * 32 + lane]);
        uint2 hv1 = hb2[(size_t)s1 * 32 + lane];
        uint2 ev2 = __ldcs(&e2[(size_t)e2i * 32 + lane]);
        uint2 hv2 = hb2[(size_t)s2 * 32 + lane];
        uint2 ev3 = __ldcs(&e2[(size_t)e3 * 32 + lane]);
        uint2 hv3 = hb2[(size_t)s3 * 32 + lane];
        ACCUM(ev0, hv0);
        ACCUM(ev1, hv1);
        ACCUM(ev2, hv2);
        ACCUM(ev3, hv3);
    }
    for (; j < jend; j++) {
        int e0 = eperm[j], s0 = sperm[j];
        uint2 ev0 = __ldcs(&e2[(size_t)e0 * 32 + lane]);
        uint2 hv0 = hb2[(size_t)s0 * 32 + lane];
        ACCUM(ev0, hv0);
    }
#undef ACCUM
    reinterpret_cast<float4*>(z)[w * 32 + lane] = acc;
}

// ---------------- pooling ----------------
__global__ void gate2_kernel(const float* __restrict__ hid, const float* __restrict__ w2,
                             const float* __restrict__ b2, float* __restrict__ gate, int n) {
    int w = (blockIdx.x * blockDim.x + threadIdx.x) >> 5;
    int lane = threadIdx.x & 31;
    if (w >= n) return;
    float s = hid[w * 64 + lane] * w2[lane] + hid[w * 64 + 32 + lane] * w2[32 + lane];
#pragma unroll
    for (int o = 16; o > 0; o >>= 1) s += __shfl_down_sync(0xffffffffu, s, o);
    if (lane == 0) gate[w] = s + b2[0];
}

__device__ __forceinline__ unsigned f2ord(float f) {
    unsigned b = __float_as_uint(f);
    return (b & 0x80000000u) ? ~b : (b | 0x80000000u);
}
__device__ __forceinline__ float ord2f(unsigned k) {
    return __uint_as_float((k & 0x80000000u) ? (k & 0x7fffffffu) : ~k);
}

__global__ void smax_kernel(const float* __restrict__ gate, const int* __restrict__ batch,
                            unsigned* __restrict__ gmaxk, int n) {
    int i = blockIdx.x * blockDim.x + threadIdx.x;
    if (i < n) atomicMax(&gmaxk[batch[i]], f2ord(gate[i]));
}

__global__ void wexp_kernel(const float* __restrict__ gate, const int* __restrict__ batch,
                            const unsigned* __restrict__ gmaxk, float* __restrict__ wexp,
                            float* __restrict__ den, int n) {
    int i = blockIdx.x * blockDim.x + threadIdx.x;
    if (i >= n) return;
    float m = ord2f(gmaxk[batch[i]]);
    float w = expf(gate[i] - m);
    wexp[i] = w;
    atomicAdd(&den[batch[i]], w);
}

// run-length pool: batch sorted; warp walks 64 consecutive nodes, flush on change
#define PCH 64
__global__ void pool_kernel(const float* __restrict__ h, const int* __restrict__ batch,
                            const float* __restrict__ wexp, const float* __restrict__ den,
                            float* __restrict__ pool, int n) {
    int wg = (blockIdx.x * blockDim.x + threadIdx.x) >> 5;
    int lane = threadIdx.x & 31;
    int base = wg * PCH;
    if (base >= n) return;
    int end = min(base + PCH, n);
    const float4* h4 = reinterpret_cast<const float4*>(h);
    int curb = -1;
    float4 acc = make_float4(0.f, 0.f, 0.f, 0.f);
    for (int node = base; node < end; node++) {
        int b = batch[node];
        if (b != curb) {
            if (curb >= 0) {
                float* p = pool + curb * HH + lane * 4;
                atomicAdd(p + 0, acc.x);
                atomicAdd(p + 1, acc.y);
                atomicAdd(p + 2, acc.z);
                atomicAdd(p + 3, acc.w);
            }
            curb = b;
            acc = make_float4(0.f, 0.f, 0.f, 0.f);
        }
        float alpha = wexp[node] / den[b];
        float4 hv = h4[(size_t)node * 32 + lane];
        acc.x += alpha * hv.x;
        acc.y += alpha * hv.y;
        acc.z += alpha * hv.z;
        acc.w += alpha * hv.w;
    }
    if (curb >= 0) {
        float* p = pool + curb * HH + lane * 4;
        atomicAdd(p + 0, acc.x);
        atomicAdd(p + 1, acc.y);
        atomicAdd(p + 2, acc.z);
        atomicAdd(p + 3, acc.w);
    }
}

__global__ void head2_kernel(const float* __restrict__ ht, const float* __restrict__ w2,
                             const float* __restrict__ b2, float* __restrict__ out,
                             int G, int T) {
    int i = blockIdx.x * blockDim.x + threadIdx.x;
    if (i >= G * T) return;
    int g = i / T, t = i - g * T;
    float s = b2[t];
    for (int k = 0; k < HH; k++) s += ht[g * HH + k] * w2[k * T + t];
    out[i] = s;
}

// ---------------- launch ----------------
extern "C" void kernel_launch(void* const* d_in, const int* in_sizes, int n_in,
                              void* d_out, int out_size) {
    const float* x = (const float*)d_in[0];
    const float* edge_attr = (const float*)d_in[1];
    const float* node_w = (const float*)d_in[2];
    const float* node_b = (const float*)d_in[3];
    const float* edge_w1 = (const float*)d_in[4];
    const float* edge_b1 = (const float*)d_in[5];
    const float* edge_w2 = (const float*)d_in[6];
    const float* edge_b2 = (const float*)d_in[7];
    const float* conv_w1 = (const float*)d_in[8];
    const float* conv_b1 = (const float*)d_in[9];
    const float* conv_w2 = (const float*)d_in[10];
    const float* conv_b2 = (const float*)d_in[11];
    const float* bn_gamma = (const float*)d_in[12];
    const float* bn_beta = (const float*)d_in[13];
    const float* gate_w1 = (const float*)d_in[14];
    const float* gate_b1 = (const float*)d_in[15];
    const float* gate_w2 = (const float*)d_in[16];
    const float* gate_b2 = (const float*)d_in[17];
    const float* head_w1 = (const float*)d_in[18];
    const float* head_b1 = (const float*)d_in[19];
    const float* head_w2 = (const float*)d_in[20];
    const float* head_b2 = (const float*)d_in[21];
    const int* edge_index = (const int*)d_in[22];
    const int* batch = (const int*)d_in[23];

    const int N = in_sizes[0] / 64;
    const int E = in_sizes[22] / 2;
    const int T = 5;
    const int G = out_size / T;

    float *h, *z, *tb, *gate, *wexp, *den, *pool, *ht;
    __half *e, *hb;
    int *deg, *off, *cur, *bsum, *eperm, *sperm;
    unsigned* gmaxk;
    cudaGetSymbolAddress((void**)&h, g_h);
    cudaGetSymbolAddress((void**)&hb, g_hb);
    cudaGetSymbolAddress((void**)&z, g_z);
    cudaGetSymbolAddress((void**)&tb, g_tb);
    cudaGetSymbolAddress((void**)&e, g_e);
    cudaGetSymbolAddress((void**)&deg, g_deg);
    cudaGetSymbolAddress((void**)&off, g_off);
    cudaGetSymbolAddress((void**)&cur, g_cur);
    cudaGetSymbolAddress((void**)&bsum, g_bsum);
    cudaGetSymbolAddress((void**)&eperm, g_eperm);
    cudaGetSymbolAddress((void**)&sperm, g_sperm);
    cudaGetSymbolAddress((void**)&gate, g_gate);
    cudaGetSymbolAddress((void**)&wexp, g_wexp);
    cudaGetSymbolAddress((void**)&gmaxk, g_gmaxk);
    cudaGetSymbolAddress((void**)&den, g_den);
    cudaGetSymbolAddress((void**)&pool, g_pool);
    cudaGetSymbolAddress((void**)&ht, g_ht);

    __half *wnh, *wnl, *c1h, *c1l, *c2h, *c2l, *wgh, *wgl, *whh, *whl,
        *e1h, *e1l, *e2h, *e2l;
    cudaGetSymbolAddress((void**)&wnh, g_wnh); cudaGetSymbolAddress((void**)&wnl, g_wnl);
    cudaGetSymbolAddress((void**)&c1h, g_c1h); cudaGetSymbolAddress((void**)&c1l, g_c1l);
    cudaGetSymbolAddress((void**)&c2h, g_c2h); cudaGetSymbolAddress((void**)&c2l, g_c2l);
    cudaGetSymbolAddress((void**)&wgh, g_wgh); cudaGetSymbolAddress((void**)&wgl, g_wgl);
    cudaGetSymbolAddress((void**)&whh, g_whh); cudaGetSymbolAddress((void**)&whl, g_whl);
    cudaGetSymbolAddress((void**)&e1h, g_e1h); cudaGetSymbolAddress((void**)&e1l, g_e1l);
    cudaGetSymbolAddress((void**)&e2h, g_e2h); cudaGetSymbolAddress((void**)&e2l, g_e2l);

    // dynamic smem sizes (bytes)
    const int SM_N1 = (2 * 128 * 72 + 2 * 64 * 136) * 2;
    const int SM_G = (2 * 128 * 136 + 2 * 128 * 72) * 2;
    const int SM_H = (2 * 128 * 136 + 2 * 128 * 136) * 2;
    const int SM_CONV = 6 * 128 * 136 * 2;
    const int SM_EDGE = (128 * 24 + 16 * 136 + 2 * 128 * 136) * 2;  // 80128 -> 2 blocks/SM
    cudaFuncSetAttribute(mma_gemm<64, 128, false, true>, cudaFuncAttributeMaxDynamicSharedMemorySize, SM_N1);
    cudaFuncSetAttribute(mma_gemm<128, 64, true, false>, cudaFuncAttributeMaxDynamicSharedMemorySize, SM_G);
    cudaFuncSetAttribute(mma_gemm<128, 128, true, false>, cudaFuncAttributeMaxDynamicSharedMemorySize, SM_H);
    cudaFuncSetAttribute(conv_fused_kernel, cudaFuncAttributeMaxDynamicSharedMemorySize, SM_CONV);
    cudaFuncSetAttribute(edge_mma_kernel, cudaFuncAttributeMaxDynamicSharedMemorySize, SM_EDGE);

    // zero scratch
    cudaMemsetAsync(deg, 0, (size_t)N * 4, 0);
    cudaMemsetAsync(cur, 0, (size_t)N * 4, 0);
    cudaMemsetAsync(gmaxk, 0, (size_t)G * 4, 0);
    cudaMemsetAsync(den, 0, (size_t)G * 4, 0);
    cudaMemsetAsync(pool, 0, (size_t)G * HH * 4, 0);

    // fused weight prep: 13 segments, one launch
    PrepArgs pa{};
    int idx = 0, woff = 0;
    auto addseg = [&](const float* s, __half* hi, __half* lo, int K, int Nn, int PB) {
        pa.a[idx].src = s; pa.a[idx].hi = hi; pa.a[idx].lo = lo;
        pa.a[idx].N = Nn; pa.a[idx].PB = PB; pa.a[idx].start = woff; pa.a[idx].count = K * PB;
        woff += K * PB; idx++;
    };
    addseg(node_w, wnh, wnl, 64, 128, 136);
    for (int l = 0; l < 4; l++)
        addseg(conv_w1 + (size_t)l * 16384, c1h + (size_t)l * 128 * 136,
               c1l + (size_t)l * 128 * 136, 128, 128, 136);
    for (int l = 0; l < 4; l++)
        addseg(conv_w2 + (size_t)l * 16384, c2h + (size_t)l * 128 * 136,
               c2l + (size_t)l * 128 * 136, 128, 128, 136);
    addseg(gate_w1, wgh, wgl, 128, 64, 72);
    addseg(head_w1, whh, whl, 128, 128, 136);
    addseg(edge_w1, e1h, e1l, 16, 128, 136);
    addseg(edge_w2, e2h, e2l, 128, 128, 136);
    pa.total = woff;
    wprep_kernel<<<(pa.total + 255) / 256, 256>>>(pa);

    // CSR by dst (multi-block scan)
    const int NB = (N + 1023) / 1024;
    hist_kernel<<<(E + 255) / 256, 256>>>(edge_index, deg, E);
    scan1_kernel<<<NB, 1024>>>(deg, off, bsum, N);
    scan2_kernel<<<1, 32>>>(bsum, NB);
    scan3_kernel<<<(N + 255) / 256, 256>>>(off, bsum, N);
    scatter_kernel<<<(E + 255) / 256, 256>>>(edge_index, off, cur, eperm, sperm, E);

    // encoders (edge hi-only fp16, sequential edge-id write)
    mma_gemm<64, 128, false, true><<<(N + 127) / 128, 256, SM_N1>>>(
        x, wnh, wnl, node_b, h, hb, N);
    edge_mma_kernel<<<(E + 127) / 128, 256, SM_EDGE>>>(
        edge_attr, e1h, e2h, edge_b1, edge_b2, e, E);

    // 4 GINE layers: aggregate (eperm gather) -> fused 2-GEMM conv
    for (int l = 0; l < 4; l++) {
        aggregate_kernel<<<(N + 7) / 8, 256>>>(h, hb, e, off, deg, eperm, sperm, z, N);
        conv_fused_kernel<<<(N + 127) / 128, 256, SM_CONV>>>(
            z, c1h + (size_t)l * 128 * 136, c1l + (size_t)l * 128 * 136,
            c2h + (size_t)l * 128 * 136, c2l + (size_t)l * 128 * 136,
            conv_b1 + l * HH, conv_b2 + l * HH,
            bn_gamma + l * HH, bn_beta + l * HH, h, hb, N);
    }

    // gate MLP + segment softmax pooling
    mma_gemm<128, 64, true, false><<<(N + 127) / 128, 256, SM_G>>>(
        h, wgh, wgl, gate_b1, tb, nullptr, N);
    gate2_kernel<<<(N + 7) / 8, 256>>>(tb, gate_w2, gate_b2, gate, N);
    smax_kernel<<<(N + 255) / 256, 256>>>(gate, batch, gmaxk, N);
    wexp_kernel<<<(N + 255) / 256, 256>>>(gate, batch, gmaxk, wexp, den, N);
    {
        int warps = (N + PCH - 1) / PCH;
        pool_kernel<<<(warps * 32 + 255) / 256, 256>>>(h, batch, wexp, den, pool, N);
    }

    // head
    mma_gemm<128, 128, true, false><<<(G + 127) / 128, 256, SM_H>>>(
        pool, whh, whl, head_b1, ht, nullptr, G);
    head2_kernel<<<(G * T + 255) / 256, 256>>>(ht, head_w2, head_b2, (float*)d_out, G, T);
}